// round 7
// baseline (speedup 1.0000x reference)
#include <cuda_runtime.h>
#include <math.h>

// ZINBDecoder, converged LDG.64 rows + packed f32x2 math, 8-edge fold:
//   - whole warp cooperates on one edge's rows: 2x LDG.64 per 512B row
//     (lane l holds f32x2 pairs l and l+32), fully coalesced
//   - 8 edges per iteration, ITERS iterations per warp
//   - weights register-resident as packed pairs (lane l: pairs l, l+32)
//   - fold 24 partials (8 edges x 3 sums) via xor16/8/4 + butterfly xor2/1;
//     quad q (lanes 4q..4q+3) ends up owning edge q's (sm, sd, sp).
// out = [mu | disp | pi], fp32.

#define ITERS 4   // 8 edges/iter -> 32 edges per warp

typedef unsigned long long u64;

__device__ __forceinline__ u64 fmul2(u64 a, u64 b) {
    u64 d;
    asm("mul.rn.f32x2 %0, %1, %2;" : "=l"(d) : "l"(a), "l"(b));
    return d;
}

__device__ __forceinline__ u64 ffma2(u64 a, u64 b, u64 c) {
    u64 d;
    asm("fma.rn.f32x2 %0, %1, %2, %3;" : "=l"(d) : "l"(a), "l"(b), "l"(c));
    return d;
}

__device__ __forceinline__ float unpack_sum(u64 p) {
    unsigned int lo, hi;
    asm("mov.b64 {%0, %1}, %2;" : "=r"(lo), "=r"(hi) : "l"(p));
    return __uint_as_float(lo) + __uint_as_float(hi);
}

__device__ __forceinline__ float fast_sigmoid(float x) {
    return __fdividef(1.0f, 1.0f + __expf(-x));
}

__global__ void __launch_bounds__(256)
zinb_kernel(const float* __restrict__ ufeats,
            const float* __restrict__ ifeats,
            const float* __restrict__ ge_factor,
            const float* __restrict__ sz_factor,
            const float* __restrict__ W_mean,
            const float* __restrict__ b_mean,
            const float* __restrict__ W_disp,
            const float* __restrict__ b_disp,
            const float* __restrict__ W_pi,
            const float* __restrict__ b_pi,
            const int*   __restrict__ src_idx,
            const int*   __restrict__ dst_idx,
            float* __restrict__ out,
            int E)
{
    const int tid  = threadIdx.x;
    const int lane = tid & 31;

    const float bm = b_mean[0];
    const float bd = b_disp[0];
    const float bp = b_pi[0];

    // Packed weight pairs in registers: pair (lane) and (lane+32).
    const u64* __restrict__ wm64 = reinterpret_cast<const u64*>(W_mean);
    const u64* __restrict__ wd64 = reinterpret_cast<const u64*>(W_disp);
    const u64* __restrict__ wp64 = reinterpret_cast<const u64*>(W_pi);
    const u64 wm0 = wm64[lane], wm1 = wm64[lane + 32];
    const u64 wd0 = wd64[lane], wd1 = wd64[lane + 32];
    const u64 wp0 = wp64[lane], wp1 = wp64[lane + 32];

    const int       gwarp = (blockIdx.x * blockDim.x + tid) >> 5;
    const long long wbase = (long long)gwarp * (8 * ITERS);

#pragma unroll 1
    for (int it = 0; it < ITERS; ++it) {
        const long long base = wbase + (long long)it * 8;
        if (base >= E) break;

        // Lanes 0..7 (replicated 4x) hold the 8 edges' indices.
        const int       jl   = lane & 7;
        const long long e_l  = base + jl;
        const int       e_lc = (e_l < E) ? (int)e_l : (E - 1);
        const int s_l = src_idx[e_lc];
        const int g_l = dst_idx[e_lc];

        float val[24];

        // Whole warp processes edge j: 2x LDG.64 per row (fully coalesced).
#pragma unroll
        for (int j = 0; j < 8; ++j) {
            const int s_j = __shfl_sync(0xFFFFFFFFu, s_l, j);
            const int g_j = __shfl_sync(0xFFFFFFFFu, g_l, j);

            const u64* __restrict__ up =
                reinterpret_cast<const u64*>(ufeats + (size_t)s_j * 128);
            const u64* __restrict__ vp =
                reinterpret_cast<const u64*>(ifeats + (size_t)g_j * 128);

            const u64 u0 = up[lane], u1 = up[lane + 32];
            const u64 v0 = vp[lane], v1 = vp[lane + 32];

            const u64 h0 = fmul2(u0, v0);
            const u64 h1 = fmul2(u1, v1);

            u64 am = fmul2(h0, wm0); am = ffma2(h1, wm1, am);
            u64 ad = fmul2(h0, wd0); ad = ffma2(h1, wd1, ad);
            u64 ap = fmul2(h0, wp0); ap = ffma2(h1, wp1, ap);

            val[3*j+0] = unpack_sum(am);
            val[3*j+1] = unpack_sum(ad);
            val[3*j+2] = unpack_sum(ap);
        }

        // ---- Fold 24 -> 12 (xor 16): edge bit2 := lane bit4.
#pragma unroll
        for (int i = 0; i < 12; ++i) {
            const bool  hi   = (lane & 16) != 0;
            const float send = hi ? val[i]      : val[i + 12];
            const float keep = hi ? val[i + 12] : val[i];
            val[i] = keep + __shfl_xor_sync(0xFFFFFFFFu, send, 16);
        }
        // ---- 12 -> 6 (xor 8): edge bit1 := lane bit3.
#pragma unroll
        for (int i = 0; i < 6; ++i) {
            const bool  hi   = (lane & 8) != 0;
            const float send = hi ? val[i]     : val[i + 6];
            const float keep = hi ? val[i + 6] : val[i];
            val[i] = keep + __shfl_xor_sync(0xFFFFFFFFu, send, 8);
        }
        // ---- 6 -> 3 (xor 4): edge bit0 := lane bit2. Quad q owns edge q.
#pragma unroll
        for (int i = 0; i < 3; ++i) {
            const bool  hi   = (lane & 4) != 0;
            const float send = hi ? val[i]     : val[i + 3];
            const float keep = hi ? val[i + 3] : val[i];
            val[i] = keep + __shfl_xor_sync(0xFFFFFFFFu, send, 4);
        }
        // ---- Butterfly within each quad (xor 2, 1).
#pragma unroll
        for (int off = 2; off >= 1; off >>= 1) {
            val[0] += __shfl_xor_sync(0xFFFFFFFFu, val[0], off);
            val[1] += __shfl_xor_sync(0xFFFFFFFFu, val[1], off);
            val[2] += __shfl_xor_sync(0xFFFFFFFFu, val[2], off);
        }

        // Leaders (lanes 0,4,...,28) handle edge (lane>>2).
        const int o   = lane >> 2;
        const int s_o = __shfl_sync(0xFFFFFFFFu, s_l, o);
        const int g_o = __shfl_sync(0xFFFFFFFFu, g_l, o);

        if ((lane & 3) == 0) {
            const long long e_ll = base + o;
            if (e_ll < E) {
                const int e = (int)e_ll;

                const float gef = ge_factor[g_o];
                const float szf = sz_factor[s_o];

                const float mu_sig = fast_sigmoid(val[0] + bm);
                const float pi_v   = fast_sigmoid(val[2] + bp);

                // stable softplus: max(x,0) + log(1 + exp(-|x|))
                const float x = gef * (val[1] + bd);
                float disp = fmaxf(x, 0.0f) + __logf(1.0f + __expf(-fabsf(x)));
                disp = fminf(fmaxf(disp, 1e-4f), 1e4f);

                float mu = __expf(gef * mu_sig) - 1.0f;   // arg in [0,1]
                mu = fminf(fmaxf(mu, 1e-5f), 1e6f);
                mu *= szf;

                out[e]                 = mu;
                out[(size_t)E + e]     = disp;
                out[(size_t)2 * E + e] = pi_v;
            }
        }
    }
}

extern "C" void kernel_launch(void* const* d_in, const int* in_sizes, int n_in,
                              void* d_out, int out_size)
{
    const float* ufeats    = (const float*)d_in[0];
    const float* ifeats    = (const float*)d_in[1];
    const float* ge_factor = (const float*)d_in[2];
    const float* sz_factor = (const float*)d_in[3];
    const float* W_mean    = (const float*)d_in[4];
    const float* b_mean    = (const float*)d_in[5];
    const float* W_disp    = (const float*)d_in[6];
    const float* b_disp    = (const float*)d_in[7];
    const float* W_pi      = (const float*)d_in[8];
    const float* b_pi      = (const float*)d_in[9];
    const int*   src_idx   = (const int*)d_in[10];
    const int*   dst_idx   = (const int*)d_in[11];
    float* out = (float*)d_out;
    (void)n_in; (void)out_size;

    const int E = in_sizes[10];

    // 32 edges per warp, 8 warps per block -> 256 edges per block.
    const int threads = 256;
    const long long edges_per_block = 8LL * 8 * ITERS;
    const int blocks = (int)(((long long)E + edges_per_block - 1) / edges_per_block);

    zinb_kernel<<<blocks, threads>>>(
        ufeats, ifeats, ge_factor, sz_factor,
        W_mean, b_mean, W_disp, b_disp, W_pi, b_pi,
        src_idx, dst_idx, out, E);
}